// round 6
// baseline (speedup 1.0000x reference)
#include <cuda_runtime.h>

#define NBLOCKS 592     // 4 CTAs/SM x 148 SMs -> exactly one wave
#define NTHREADS 256

// Per-block partials (overwritten every call — no zeroing needed).
__device__ float        g_part_iou[NBLOCKS];
__device__ float        g_part_mse[NBLOCKS];
__device__ unsigned int g_part_ninc[NBLOCKS];
// Completion counter; the last block resets it to 0 -> replay-safe.
__device__ unsigned int g_done_count = 0;

__device__ __forceinline__ float4 ldcs4(const float4* p) {
    return __ldcs(p);   // streaming (evict-first): no reuse, don't pollute L2
}

__device__ __forceinline__ void process_box(const float4 p, const float4 g,
                                            float& iou_acc, float& mse_acc,
                                            unsigned int& ninc)
{
    // gt corners (cx, cy, w, h -> xyxy)
    float xminT = g.x - g.z * 0.5f;
    float xmaxT = g.x + g.z * 0.5f;
    float yminT = g.y - g.w * 0.5f;
    float ymaxT = g.y + g.w * 0.5f;
    // pred corners clipped to [0,1]
    float xminP = fmaxf(p.x - p.z * 0.5f, 0.0f);
    float xmaxP = fminf(p.x + p.z * 0.5f, 1.0f);
    float yminP = fmaxf(p.y - p.w * 0.5f, 0.0f);
    float ymaxP = fminf(p.y + p.w * 0.5f, 1.0f);
    // overlap box
    float o0 = fmaxf(xminT, xminP);
    float o1 = fmaxf(yminT, yminP);
    float o2 = fminf(xmaxT, xmaxP);
    float o3 = fminf(ymaxT, ymaxP);

    bool incorrect = (o2 < o0) || (o3 < o1);
    if (incorrect) {
        float dx = p.x - g.x;
        float dy = p.y - g.y;
        float dz = p.z - g.z;
        float dw = p.w - g.w;
        mse_acc += dx * dx + dy * dy + dz * dz + dw * dw;
        ninc++;
    } else {
        float area_p = p.z * p.w;
        float area_g = g.z * g.w;
        float inter  = (o2 - o0) * (o3 - o1);
        iou_acc += inter / (area_p + area_g - inter + 1e-7f);
    }
}

__global__ __launch_bounds__(NTHREADS, 4) void iou_fused_kernel(
    const float4* __restrict__ pr, const float4* __restrict__ gt,
    float* __restrict__ out, int n)
{
    float iou_acc = 0.0f, mse_acc = 0.0f;
    unsigned int ninc = 0u;

    const int tid    = blockIdx.x * NTHREADS + threadIdx.x;
    const int stride = NBLOCKS * NTHREADS;

    int i = tid;
    // Unroll x6: 12 independent 128-bit loads in flight per trip.
    for (; i + 5 * stride < n; i += 6 * stride) {
        float4 p0 = ldcs4(&pr[i]);
        float4 g0 = ldcs4(&gt[i]);
        float4 p1 = ldcs4(&pr[i + stride]);
        float4 g1 = ldcs4(&gt[i + stride]);
        float4 p2 = ldcs4(&pr[i + 2 * stride]);
        float4 g2 = ldcs4(&gt[i + 2 * stride]);
        float4 p3 = ldcs4(&pr[i + 3 * stride]);
        float4 g3 = ldcs4(&gt[i + 3 * stride]);
        float4 p4 = ldcs4(&pr[i + 4 * stride]);
        float4 g4 = ldcs4(&gt[i + 4 * stride]);
        float4 p5 = ldcs4(&pr[i + 5 * stride]);
        float4 g5 = ldcs4(&gt[i + 5 * stride]);
        process_box(p0, g0, iou_acc, mse_acc, ninc);
        process_box(p1, g1, iou_acc, mse_acc, ninc);
        process_box(p2, g2, iou_acc, mse_acc, ninc);
        process_box(p3, g3, iou_acc, mse_acc, ninc);
        process_box(p4, g4, iou_acc, mse_acc, ninc);
        process_box(p5, g5, iou_acc, mse_acc, ninc);
    }
    for (; i < n; i += stride) {
        process_box(ldcs4(&pr[i]), ldcs4(&gt[i]), iou_acc, mse_acc, ninc);
    }

    // Intra-warp reduce
    #pragma unroll
    for (int off = 16; off > 0; off >>= 1) {
        iou_acc += __shfl_down_sync(0xFFFFFFFFu, iou_acc, off);
        mse_acc += __shfl_down_sync(0xFFFFFFFFu, mse_acc, off);
        ninc    += __shfl_down_sync(0xFFFFFFFFu, ninc, off);
    }

    // Inter-warp reduce via smem
    __shared__ float s_iou[NTHREADS / 32];
    __shared__ float s_mse[NTHREADS / 32];
    __shared__ unsigned int s_ninc[NTHREADS / 32];
    const int lane = threadIdx.x & 31;
    const int warp = threadIdx.x >> 5;
    if (lane == 0) {
        s_iou[warp]  = iou_acc;
        s_mse[warp]  = mse_acc;
        s_ninc[warp] = ninc;
    }
    __syncthreads();
    if (warp == 0) {
        const int nw = NTHREADS / 32;
        float iou = (lane < nw) ? s_iou[lane] : 0.0f;
        float mse = (lane < nw) ? s_mse[lane] : 0.0f;
        unsigned int ni = (lane < nw) ? s_ninc[lane] : 0u;
        #pragma unroll
        for (int off = 4; off > 0; off >>= 1) {
            iou += __shfl_down_sync(0xFFFFFFFFu, iou, off);
            mse += __shfl_down_sync(0xFFFFFFFFu, mse, off);
            ni  += __shfl_down_sync(0xFFFFFFFFu, ni, off);
        }
        if (lane == 0) {
            g_part_iou[blockIdx.x]  = iou;
            g_part_mse[blockIdx.x]  = mse;
            g_part_ninc[blockIdx.x] = ni;
            // ncorr total = n - total ninc (derived in finalize)
        }
    }

    // Last-block-done finalization
    __shared__ bool is_last;
    if (threadIdx.x == 0) {
        __threadfence();
        unsigned int prev = atomicAdd(&g_done_count, 1u);
        is_last = (prev == (unsigned int)(gridDim.x - 1));
    }
    __syncthreads();
    if (!is_last) return;

    float iou = 0.0f, mse = 0.0f;
    unsigned long long ni = 0ull;
    for (int j = threadIdx.x; j < NBLOCKS; j += NTHREADS) {
        iou += g_part_iou[j];
        mse += g_part_mse[j];
        ni  += g_part_ninc[j];
    }
    #pragma unroll
    for (int off = 16; off > 0; off >>= 1) {
        iou += __shfl_down_sync(0xFFFFFFFFu, iou, off);
        mse += __shfl_down_sync(0xFFFFFFFFu, mse, off);
        ni  += __shfl_down_sync(0xFFFFFFFFu, ni, off);
    }
    __shared__ float f_iou[NTHREADS / 32];
    __shared__ float f_mse[NTHREADS / 32];
    __shared__ unsigned long long f_ninc[NTHREADS / 32];
    if (lane == 0) {
        f_iou[warp] = iou; f_mse[warp] = mse; f_ninc[warp] = ni;
    }
    __syncthreads();
    if (threadIdx.x == 0) {
        const int nw = NTHREADS / 32;
        double diou = 0.0, dmse = 0.0;
        unsigned long long tninc = 0ull;
        for (int w = 0; w < nw; w++) {
            diou += (double)f_iou[w];
            dmse += (double)f_mse[w];
            tninc += f_ninc[w];
        }
        unsigned long long tncorr = (unsigned long long)n - tninc;
        double mse_denom  = (double)(tninc * 4ull > 0ull ? tninc * 4ull : 1ull);
        double corr_denom = (double)(tncorr > 0ull ? tncorr : 1ull);
        float mse_mean = (float)(dmse / mse_denom);
        float iou_mean = (float)(diou / corr_denom);
        float res_full = iou_mean + (tninc > 0ull ? -mse_mean : 0.0f);
        out[0] = (tncorr > 0ull) ? res_full : -mse_mean;
        g_done_count = 0u;  // reset for next graph replay
    }
}

extern "C" void kernel_launch(void* const* d_in, const int* in_sizes, int n_in,
                              void* d_out, int out_size) {
    const float4* pr = (const float4*)d_in[0];
    const float4* gt = (const float4*)d_in[1];
    float* out = (float*)d_out;
    int n = in_sizes[0] / 4;  // floats -> boxes

    iou_fused_kernel<<<NBLOCKS, NTHREADS>>>(pr, gt, out, n);
}

// round 8
// speedup vs baseline: 1.0295x; 1.0295x over previous
#include <cuda_runtime.h>
#include <cstdint>

#define NBLOCKS   296      // 2 CTAs/SM x 148 SMs -> one wave (smem-limited)
#define NTHREADS  256
#define TILE_BOXES 1024    // 16 KB per array per tile
#define STAGES    3

// Per-block partials (overwritten every call).
__device__ float        g_part_iou[NBLOCKS];
__device__ float        g_part_mse[NBLOCKS];
__device__ unsigned int g_part_ninc[NBLOCKS];
__device__ unsigned int g_part_ncorr[NBLOCKS];
__device__ unsigned int g_done_count = 0;

__device__ __forceinline__ uint32_t smem_u32(const void* p) {
    uint32_t a;
    asm("{ .reg .u64 t; cvta.to.shared.u64 t, %1; cvt.u32.u64 %0, t; }"
        : "=r"(a) : "l"(p));
    return a;
}

#define MBAR_INIT(addr, cnt) \
    asm volatile("mbarrier.init.shared.b64 [%0], %1;" :: "r"(addr), "r"(cnt) : "memory")

#define MBAR_EXPECT_TX(addr, bytes) \
    asm volatile("mbarrier.arrive.expect_tx.shared.b64 _, [%0], %1;" \
                 :: "r"(addr), "r"(bytes) : "memory")

#define MBAR_ARRIVE(addr) \
    asm volatile("mbarrier.arrive.shared.b64 _, [%0];" :: "r"(addr) : "memory")

#define MBAR_WAIT(addr, parity) do {                                          \
    uint32_t _m = (addr); uint32_t _p = (parity); uint32_t _done;             \
    asm volatile(                                                             \
        "{\n\t.reg .pred p;\n\t"                                              \
        "mbarrier.try_wait.parity.acquire.cta.shared::cta.b64 p, [%1], %2;\n\t" \
        "selp.b32 %0, 1, 0, p;\n\t}"                                          \
        : "=r"(_done) : "r"(_m), "r"(_p) : "memory");                         \
    if (!_done) {                                                             \
        asm volatile(                                                         \
            "{\n\t.reg .pred P1;\n\t"                                         \
            "WL_%=:\n\t"                                                      \
            "mbarrier.try_wait.parity.acquire.cta.shared::cta.b64 P1, [%0], %1, 0x989680;\n\t" \
            "@P1 bra.uni WD_%=;\n\t"                                          \
            "bra.uni WL_%=;\n\t"                                              \
            "WD_%=:\n\t}"                                                     \
            :: "r"(_m), "r"(_p) : "memory");                                  \
    }                                                                         \
} while (0)

#define BULK_G2S(dst_smem, src_gmem, bytes, mbar) \
    asm volatile("cp.async.bulk.shared::cta.global.mbarrier::complete_tx::bytes " \
                 "[%0], [%1], %2, [%3];" \
                 :: "r"(dst_smem), "l"(src_gmem), "r"(bytes), "r"(mbar) : "memory")

__device__ __forceinline__ void process_box(const float4 p, const float4 g,
                                            float& iou_acc, float& mse_acc,
                                            unsigned int& ninc, unsigned int& ncorr)
{
    float xminT = g.x - g.z * 0.5f;
    float xmaxT = g.x + g.z * 0.5f;
    float yminT = g.y - g.w * 0.5f;
    float ymaxT = g.y + g.w * 0.5f;
    float xminP = fmaxf(p.x - p.z * 0.5f, 0.0f);
    float xmaxP = fminf(p.x + p.z * 0.5f, 1.0f);
    float yminP = fmaxf(p.y - p.w * 0.5f, 0.0f);
    float ymaxP = fminf(p.y + p.w * 0.5f, 1.0f);
    float o0 = fmaxf(xminT, xminP);
    float o1 = fmaxf(yminT, yminP);
    float o2 = fminf(xmaxT, xmaxP);
    float o3 = fminf(ymaxT, ymaxP);

    bool incorrect = (o2 < o0) || (o3 < o1);
    if (incorrect) {
        float dx = p.x - g.x;
        float dy = p.y - g.y;
        float dz = p.z - g.z;
        float dw = p.w - g.w;
        mse_acc += dx * dx + dy * dy + dz * dz + dw * dw;
        ninc++;
    } else {
        float area_p = p.z * p.w;
        float area_g = g.z * g.w;
        float inter  = (o2 - o0) * (o3 - o1);
        iou_acc += __fdividef(inter, area_p + area_g - inter + 1e-7f);
        ncorr++;
    }
}

__global__ __launch_bounds__(NTHREADS, 2) void iou_tma_kernel(
    const float4* __restrict__ pr, const float4* __restrict__ gt,
    float* __restrict__ out, int n)
{
    extern __shared__ __align__(16) unsigned char smem_raw[];
    float4* prb = (float4*)smem_raw;                 // [STAGES][TILE_BOXES]
    float4* gtb = prb + STAGES * TILE_BOXES;         // [STAGES][TILE_BOXES]
    uint64_t* bars = (uint64_t*)(gtb + STAGES * TILE_BOXES);
    const uint32_t bar_base = smem_u32(bars);
    // full[s] = bar_base + s*8 ; empty[s] = bar_base + (STAGES+s)*8

    const int tid = threadIdx.x;
    const int bid = blockIdx.x;

    if (tid == 0) {
        #pragma unroll
        for (int s = 0; s < STAGES; s++) {
            MBAR_INIT(bar_base + s * 8, 1);                      // full: tx-based
            MBAR_INIT(bar_base + (STAGES + s) * 8, NTHREADS);    // empty: all threads
        }
    }
    __syncthreads();

    const int ntiles = (n + TILE_BOXES - 1) / TILE_BOXES;
    int my_tiles = (bid < ntiles) ? (ntiles - bid + NBLOCKS - 1) / NBLOCKS : 0;

    // Prologue: fill pipeline
    if (tid == 0) {
        int npre = my_tiles < STAGES ? my_tiles : STAGES;
        for (int k = 0; k < npre; k++) {
            int t = bid + k * NBLOCKS;
            int boxes = n - t * TILE_BOXES;
            if (boxes > TILE_BOXES) boxes = TILE_BOXES;
            uint32_t bytes = (uint32_t)boxes * 16u;
            uint32_t fb = bar_base + k * 8;
            MBAR_EXPECT_TX(fb, 2u * bytes);
            BULK_G2S(smem_u32(&prb[k * TILE_BOXES]), pr + (size_t)t * TILE_BOXES, bytes, fb);
            BULK_G2S(smem_u32(&gtb[k * TILE_BOXES]), gt + (size_t)t * TILE_BOXES, bytes, fb);
        }
    }

    float iou_acc = 0.0f, mse_acc = 0.0f;
    unsigned int ninc = 0u, ncorr = 0u;

    for (int it = 0; it < my_tiles; it++) {
        const int s = it % STAGES;
        const int w = it / STAGES;
        const uint32_t fb = bar_base + s * 8;
        const uint32_t eb = bar_base + (STAGES + s) * 8;

        MBAR_WAIT(fb, w & 1);

        int t = bid + it * NBLOCKS;
        int boxes = n - t * TILE_BOXES;
        if (boxes > TILE_BOXES) boxes = TILE_BOXES;

        const float4* __restrict__ ps = &prb[s * TILE_BOXES];
        const float4* __restrict__ gs = &gtb[s * TILE_BOXES];
        for (int j = tid; j < boxes; j += NTHREADS) {
            float4 p = ps[j];
            float4 g = gs[j];
            process_box(p, g, iou_acc, mse_acc, ninc, ncorr);
        }

        MBAR_ARRIVE(eb);

        // Refill this stage with tile it+STAGES (producer = tid 0)
        int nxt = it + STAGES;
        if (tid == 0 && nxt < my_tiles) {
            MBAR_WAIT(eb, w & 1);   // wait for all consumers of wrap w
            int t2 = bid + nxt * NBLOCKS;
            int boxes2 = n - t2 * TILE_BOXES;
            if (boxes2 > TILE_BOXES) boxes2 = TILE_BOXES;
            uint32_t bytes2 = (uint32_t)boxes2 * 16u;
            MBAR_EXPECT_TX(fb, 2u * bytes2);
            BULK_G2S(smem_u32(&prb[s * TILE_BOXES]), pr + (size_t)t2 * TILE_BOXES, bytes2, fb);
            BULK_G2S(smem_u32(&gtb[s * TILE_BOXES]), gt + (size_t)t2 * TILE_BOXES, bytes2, fb);
        }
    }

    // ---- Block reduction ----
    #pragma unroll
    for (int off = 16; off > 0; off >>= 1) {
        iou_acc += __shfl_down_sync(0xFFFFFFFFu, iou_acc, off);
        mse_acc += __shfl_down_sync(0xFFFFFFFFu, mse_acc, off);
        ninc    += __shfl_down_sync(0xFFFFFFFFu, ninc, off);
        ncorr   += __shfl_down_sync(0xFFFFFFFFu, ncorr, off);
    }

    __shared__ float s_iou[NTHREADS / 32];
    __shared__ float s_mse[NTHREADS / 32];
    __shared__ unsigned int s_ninc[NTHREADS / 32];
    __shared__ unsigned int s_ncorr[NTHREADS / 32];
    const int lane = threadIdx.x & 31;
    const int warp = threadIdx.x >> 5;
    if (lane == 0) {
        s_iou[warp] = iou_acc; s_mse[warp] = mse_acc;
        s_ninc[warp] = ninc;   s_ncorr[warp] = ncorr;
    }
    __syncthreads();
    if (warp == 0) {
        const int nw = NTHREADS / 32;
        float iou = (lane < nw) ? s_iou[lane] : 0.0f;
        float mse = (lane < nw) ? s_mse[lane] : 0.0f;
        unsigned int ni = (lane < nw) ? s_ninc[lane]  : 0u;
        unsigned int nc = (lane < nw) ? s_ncorr[lane] : 0u;
        #pragma unroll
        for (int off = 4; off > 0; off >>= 1) {
            iou += __shfl_down_sync(0xFFFFFFFFu, iou, off);
            mse += __shfl_down_sync(0xFFFFFFFFu, mse, off);
            ni  += __shfl_down_sync(0xFFFFFFFFu, ni, off);
            nc  += __shfl_down_sync(0xFFFFFFFFu, nc, off);
        }
        if (lane == 0) {
            g_part_iou[bid]   = iou;
            g_part_mse[bid]   = mse;
            g_part_ninc[bid]  = ni;
            g_part_ncorr[bid] = nc;
        }
    }

    // ---- Last-block finalization ----
    __shared__ bool is_last;
    if (threadIdx.x == 0) {
        __threadfence();
        unsigned int prev = atomicAdd(&g_done_count, 1u);
        is_last = (prev == (unsigned int)(gridDim.x - 1));
    }
    __syncthreads();
    if (!is_last) return;

    float iou = 0.0f, mse = 0.0f;
    unsigned long long ni = 0ull, nc = 0ull;
    for (int j = threadIdx.x; j < NBLOCKS; j += NTHREADS) {
        iou += g_part_iou[j];
        mse += g_part_mse[j];
        ni  += g_part_ninc[j];
        nc  += g_part_ncorr[j];
    }
    #pragma unroll
    for (int off = 16; off > 0; off >>= 1) {
        iou += __shfl_down_sync(0xFFFFFFFFu, iou, off);
        mse += __shfl_down_sync(0xFFFFFFFFu, mse, off);
        ni  += __shfl_down_sync(0xFFFFFFFFu, ni, off);
        nc  += __shfl_down_sync(0xFFFFFFFFu, nc, off);
    }
    __shared__ float f_iou[NTHREADS / 32];
    __shared__ float f_mse[NTHREADS / 32];
    __shared__ unsigned long long f_ni[NTHREADS / 32];
    __shared__ unsigned long long f_nc[NTHREADS / 32];
    if (lane == 0) {
        f_iou[warp] = iou; f_mse[warp] = mse; f_ni[warp] = ni; f_nc[warp] = nc;
    }
    __syncthreads();
    if (threadIdx.x == 0) {
        const int nw = NTHREADS / 32;
        double diou = 0.0, dmse = 0.0;
        unsigned long long tninc = 0ull, tncorr = 0ull;
        for (int v = 0; v < nw; v++) {
            diou += (double)f_iou[v];
            dmse += (double)f_mse[v];
            tninc += f_ni[v];
            tncorr += f_nc[v];
        }
        double mse_denom  = (double)(tninc * 4ull > 0ull ? tninc * 4ull : 1ull);
        double corr_denom = (double)(tncorr > 0ull ? tncorr : 1ull);
        float mse_mean = (float)(dmse / mse_denom);
        float iou_mean = (float)(diou / corr_denom);
        float res_full = iou_mean + (tninc > 0ull ? -mse_mean : 0.0f);
        out[0] = (tncorr > 0ull) ? res_full : -mse_mean;
        g_done_count = 0u;  // reset for next graph replay
    }
}

extern "C" void kernel_launch(void* const* d_in, const int* in_sizes, int n_in,
                              void* d_out, int out_size) {
    const float4* pr = (const float4*)d_in[0];
    const float4* gt = (const float4*)d_in[1];
    float* out = (float*)d_out;
    int n = in_sizes[0] / 4;

    const int smem_bytes = STAGES * TILE_BOXES * 16 * 2 + STAGES * 2 * 8 + 16;
    cudaFuncSetAttribute(iou_tma_kernel,
                         cudaFuncAttributeMaxDynamicSharedMemorySize, smem_bytes);
    iou_tma_kernel<<<NBLOCKS, NTHREADS, smem_bytes>>>(pr, gt, out, n);
}